// round 2
// baseline (speedup 1.0000x reference)
#include <cuda_runtime.h>
#include <math.h>

#define DEVFN __device__ __forceinline__

constexpr int G_MAX = 131072;
__device__ float g_res[(size_t)G_MAX * 64];

// tanh via exp2 + rcp approx: tanh(x) = 1 - 2/(1+exp(2x)).  ~1e-6 rel error for O(1) inputs.
DEVFN float ftanh(float x) {
    float e;
    asm("ex2.approx.f32 %0, %1;" : "=f"(e) : "f"(x * 2.885390081777927f)); // 2*log2(e)
    float r;
    asm("rcp.approx.f32 %0, %1;" : "=f"(r) : "f"(e + 1.0f));
    return fmaf(-2.0f, r, 1.0f);
}

// ---------------------------------------------------------------------------
// Shared-memory layouts
// ---------------------------------------------------------------------------
// Pair-interleaved weights: Wpair[k*32 + j] = { W[k][j], W[k][j+32] }
struct SmemConv {
    float2 Wp1[2048], Ws1[2048], Wn1[2048];
    float2 Wp2[2048], Ws2[2048], Wn2[2048];
    float  bp1[64], b1[64], bp2[64], b2[64];
    float  xs[8][384];   // per-warp activation tile (x rows, then h1 rows)
    float  aux[8][64];   // per-warp: neigh / s1 / neigh2 (phased reuse)
};   // 98304 + 1024 + 12288 + 2048 = 113664 B  -> 2 blocks/SM

struct SmemMlp {
    float2 W1[2][2048], W2[2][2048], W3[2][2048];
    float  W4[2][128];               // [t][k*2+o], same layout as source
    float  B1[128], B2[128], B3[128], B4[4];
    float  rs[8][64];                // per-warp res
    float  bufA[8][128], bufB[8][128];  // per-warp [t*64 + c] ping-pong
};   // 98304 + 1024 + 1552 + 2048 + 8192 = 111120 B -> 2 blocks/SM

DEVFN void stage_pairs(float2* dst, const float* __restrict__ src, int tid, int nt) {
    for (int idx = tid; idx < 2048; idx += nt) {
        int k = idx >> 5, j = idx & 31;
        dst[idx] = make_float2(src[k * 64 + j], src[k * 64 + j + 32]);
    }
}

// 64-k dot for 2 output columns; v read via float4 broadcasts, W pair-interleaved.
DEVFN float2 dot64(float2 init, const float* v, const float2* W, int j) {
    float2 aA = init, aB = make_float2(0.f, 0.f);
#pragma unroll 4
    for (int k4 = 0; k4 < 16; k4++) {
        float4 x  = *(const float4*)(v + k4 * 4);
        float2 w0 = W[(k4 * 4 + 0) * 32 + j];
        float2 w1 = W[(k4 * 4 + 1) * 32 + j];
        float2 w2 = W[(k4 * 4 + 2) * 32 + j];
        float2 w3 = W[(k4 * 4 + 3) * 32 + j];
        aA.x = fmaf(x.x, w0.x, aA.x); aA.y = fmaf(x.x, w0.y, aA.y);
        aA.x = fmaf(x.y, w1.x, aA.x); aA.y = fmaf(x.y, w1.y, aA.y);
        aB.x = fmaf(x.z, w2.x, aB.x); aB.y = fmaf(x.z, w2.y, aB.y);
        aB.x = fmaf(x.w, w3.x, aB.x); aB.y = fmaf(x.w, w3.y, aB.y);
    }
    return make_float2(aA.x + aB.x, aA.y + aB.y);
}

// 6-row x [6,64] against one weight matrix -> accumulate into acc[6] (2 cols/lane)
DEVFN void gemm6(float2 acc[6], const float* xs, const float2* W, int j) {
#pragma unroll 2
    for (int k4 = 0; k4 < 16; k4++) {
        float2 w0 = W[(k4 * 4 + 0) * 32 + j];
        float2 w1 = W[(k4 * 4 + 1) * 32 + j];
        float2 w2 = W[(k4 * 4 + 2) * 32 + j];
        float2 w3 = W[(k4 * 4 + 3) * 32 + j];
#pragma unroll
        for (int i = 0; i < 6; i++) {
            float4 x = *(const float4*)(xs + i * 64 + k4 * 4);
            acc[i].x = fmaf(x.x, w0.x, acc[i].x); acc[i].y = fmaf(x.x, w0.y, acc[i].y);
            acc[i].x = fmaf(x.y, w1.x, acc[i].x); acc[i].y = fmaf(x.y, w1.y, acc[i].y);
            acc[i].x = fmaf(x.z, w2.x, acc[i].x); acc[i].y = fmaf(x.z, w2.y, acc[i].y);
            acc[i].x = fmaf(x.w, w3.x, acc[i].x); acc[i].y = fmaf(x.w, w3.y, acc[i].y);
        }
    }
}

// Fused: 6-row x against TWO weight matrices (shares activation broadcasts)
DEVFN void gemm6_dual(float2 accA[6], float2 accB[6], const float* xs,
                      const float2* WA, const float2* WB, int j) {
#pragma unroll 2
    for (int k4 = 0; k4 < 16; k4++) {
        float2 a0 = WA[(k4 * 4 + 0) * 32 + j];
        float2 a1 = WA[(k4 * 4 + 1) * 32 + j];
        float2 a2 = WA[(k4 * 4 + 2) * 32 + j];
        float2 a3 = WA[(k4 * 4 + 3) * 32 + j];
        float2 c0 = WB[(k4 * 4 + 0) * 32 + j];
        float2 c1 = WB[(k4 * 4 + 1) * 32 + j];
        float2 c2 = WB[(k4 * 4 + 2) * 32 + j];
        float2 c3 = WB[(k4 * 4 + 3) * 32 + j];
#pragma unroll
        for (int i = 0; i < 6; i++) {
            float4 x = *(const float4*)(xs + i * 64 + k4 * 4);
            accA[i].x = fmaf(x.x, a0.x, accA[i].x); accA[i].y = fmaf(x.x, a0.y, accA[i].y);
            accA[i].x = fmaf(x.y, a1.x, accA[i].x); accA[i].y = fmaf(x.y, a1.y, accA[i].y);
            accA[i].x = fmaf(x.z, a2.x, accA[i].x); accA[i].y = fmaf(x.z, a2.y, accA[i].y);
            accA[i].x = fmaf(x.w, a3.x, accA[i].x); accA[i].y = fmaf(x.w, a3.y, accA[i].y);
            accB[i].x = fmaf(x.x, c0.x, accB[i].x); accB[i].y = fmaf(x.x, c0.y, accB[i].y);
            accB[i].x = fmaf(x.y, c1.x, accB[i].x); accB[i].y = fmaf(x.y, c1.y, accB[i].y);
            accB[i].x = fmaf(x.z, c2.x, accB[i].x); accB[i].y = fmaf(x.z, c2.y, accB[i].y);
            accB[i].x = fmaf(x.w, c3.x, accB[i].x); accB[i].y = fmaf(x.w, c3.y, accB[i].y);
        }
    }
}

// ---------------------------------------------------------------------------
// Kernel 1: conv1 + conv2 + mean-pool  ->  g_res[G][64]
// warp-per-group, lane j owns output columns {j, j+32}
// ---------------------------------------------------------------------------
__global__ void __launch_bounds__(256, 2)
conv_kernel(const float* __restrict__ obs,
            const float* __restrict__ Wp1, const float* __restrict__ bp1,
            const float* __restrict__ Ws1, const float* __restrict__ Wn1,
            const float* __restrict__ b1,
            const float* __restrict__ Wp2, const float* __restrict__ bp2,
            const float* __restrict__ Ws2, const float* __restrict__ Wn2,
            const float* __restrict__ b2,
            int G)
{
    extern __shared__ char smem_raw[];
    SmemConv* S = (SmemConv*)smem_raw;
    const int tid = threadIdx.x;

    stage_pairs(S->Wp1, Wp1, tid, 256);
    stage_pairs(S->Ws1, Ws1, tid, 256);
    stage_pairs(S->Wn1, Wn1, tid, 256);
    stage_pairs(S->Wp2, Wp2, tid, 256);
    stage_pairs(S->Ws2, Ws2, tid, 256);
    stage_pairs(S->Wn2, Wn2, tid, 256);
    if (tid < 64) {
        S->bp1[tid] = bp1[tid]; S->b1[tid] = b1[tid];
        S->bp2[tid] = bp2[tid]; S->b2[tid] = b2[tid];
    }
    __syncthreads();

    const int wid = tid >> 5, j = tid & 31;
    float* xs  = S->xs[wid];
    float* aux = S->aux[wid];
    const int wglobal = blockIdx.x * 8 + wid;
    const int wstride = gridDim.x * 8;

    for (int g = wglobal; g < G; g += wstride) {
        // stage x = obs[g]  (6x64)
        const float* xg = obs + (size_t)g * 384;
#pragma unroll
        for (int t = 0; t < 12; t++) xs[t * 32 + j] = xg[t * 32 + j];
        __syncwarp();

        // ---- conv1: fused pool-proj (P) and self-proj (Sacc) ----
        float2 accP[6], accS[6];
        const float2 bP = make_float2(S->bp1[j], S->bp1[j + 32]);
#pragma unroll
        for (int i = 0; i < 6; i++) { accP[i] = bP; accS[i] = make_float2(0.f, 0.f); }
        gemm6_dual(accP, accS, xs, S->Wp1, S->Ws1, j);

        // neigh = max_i relu(p_i) = max(max_i p_i, 0)
        float2 nb = make_float2(0.f, 0.f);
#pragma unroll
        for (int i = 0; i < 6; i++) {
            nb.x = fmaxf(nb.x, accP[i].x);
            nb.y = fmaxf(nb.y, accP[i].y);
        }
        aux[j] = nb.x; aux[j + 32] = nb.y;
        __syncwarp();

        // neigh-term (shared across rows) + bias
        float2 nt = dot64(make_float2(S->b1[j], S->b1[j + 32]), aux, S->Wn1, j);

        // h1 = tanh(self + nt); write back into xs; also row-sum s1
        float2 s1 = make_float2(0.f, 0.f);
#pragma unroll
        for (int i = 0; i < 6; i++) {
            float hx = ftanh(accS[i].x + nt.x);
            float hy = ftanh(accS[i].y + nt.y);
            s1.x += hx; s1.y += hy;
            xs[i * 64 + j]      = hx;
            xs[i * 64 + j + 32] = hy;
        }
        __syncwarp();                 // all lanes done reading aux(nb) & writing h1
        aux[j] = s1.x; aux[j + 32] = s1.y;
        __syncwarp();

        // ---- conv2 ----
        // self-term collapses under the mean: ss = sum_k s1[k] * Ws2[k][c]
        float2 ss = dot64(make_float2(0.f, 0.f), aux, S->Ws2, j);

        // pool-proj on h1 rows
        float2 accP2[6];
        const float2 bP2 = make_float2(S->bp2[j], S->bp2[j + 32]);
#pragma unroll
        for (int i = 0; i < 6; i++) accP2[i] = bP2;
        gemm6(accP2, xs, S->Wp2, j);
        float2 nb2 = make_float2(0.f, 0.f);
#pragma unroll
        for (int i = 0; i < 6; i++) {
            nb2.x = fmaxf(nb2.x, accP2[i].x);
            nb2.y = fmaxf(nb2.y, accP2[i].y);
        }
        __syncwarp();                 // all lanes done reading aux(s1)
        aux[j] = nb2.x; aux[j + 32] = nb2.y;
        __syncwarp();

        float2 nt2 = dot64(make_float2(S->b2[j], S->b2[j + 32]), aux, S->Wn2, j);

        // res = mean_i h2[i] = nt2 + b2 + ss/6
        float* rg = g_res + (size_t)g * 64;
        rg[j]      = fmaf(ss.x, 1.0f / 6.0f, nt2.x);
        rg[j + 32] = fmaf(ss.y, 1.0f / 6.0f, nt2.y);
        __syncwarp();
    }
}

// ---------------------------------------------------------------------------
// Kernel 2: per-type actor MLPs + output scatter
// ---------------------------------------------------------------------------
__global__ void __launch_bounds__(256, 2)
mlp_kernel(const float* __restrict__ MW1, const float* __restrict__ Mb1,
           const float* __restrict__ MW2, const float* __restrict__ Mb2,
           const float* __restrict__ MW3, const float* __restrict__ Mb3,
           const float* __restrict__ MW4, const float* __restrict__ Mb4,
           float* __restrict__ out, int G)
{
    extern __shared__ char smem_raw[];
    SmemMlp* S = (SmemMlp*)smem_raw;
    const int tid = threadIdx.x;

    stage_pairs(S->W1[0], MW1,        tid, 256);
    stage_pairs(S->W1[1], MW1 + 4096, tid, 256);
    stage_pairs(S->W2[0], MW2,        tid, 256);
    stage_pairs(S->W2[1], MW2 + 4096, tid, 256);
    stage_pairs(S->W3[0], MW3,        tid, 256);
    stage_pairs(S->W3[1], MW3 + 4096, tid, 256);
    if (tid < 256) ((float*)S->W4)[tid] = MW4[tid];
    if (tid < 128) { S->B1[tid] = Mb1[tid]; S->B2[tid] = Mb2[tid]; S->B3[tid] = Mb3[tid]; }
    if (tid < 4)   S->B4[tid] = Mb4[tid];
    __syncthreads();

    const int wid = tid >> 5, j = tid & 31;
    float* rs = S->rs[wid];
    float* bA = S->bufA[wid];
    float* bB = S->bufB[wid];
    const int wglobal = blockIdx.x * 8 + wid;
    const int wstride = gridDim.x * 8;

    for (int g = wglobal; g < G; g += wstride) {
        const float* rg = g_res + (size_t)g * 64;
        rs[j] = rg[j]; rs[j + 32] = rg[j + 32];
        __syncwarp();

        // layer 1 (shared input res)
        float2 a0 = dot64(make_float2(S->B1[j],      S->B1[j + 32]),      rs, S->W1[0], j);
        float2 a1 = dot64(make_float2(S->B1[64 + j], S->B1[96 + j]),      rs, S->W1[1], j);
        bA[j]       = fmaxf(a0.x, 0.f); bA[j + 32]  = fmaxf(a0.y, 0.f);
        bA[64 + j]  = fmaxf(a1.x, 0.f); bA[96 + j]  = fmaxf(a1.y, 0.f);
        __syncwarp();

        // layer 2
        float2 c0 = dot64(make_float2(S->B2[j],      S->B2[j + 32]),      bA,      S->W2[0], j);
        float2 c1 = dot64(make_float2(S->B2[64 + j], S->B2[96 + j]),      bA + 64, S->W2[1], j);
        bB[j]       = fmaxf(c0.x, 0.f); bB[j + 32]  = fmaxf(c0.y, 0.f);
        bB[64 + j]  = fmaxf(c1.x, 0.f); bB[96 + j]  = fmaxf(c1.y, 0.f);
        __syncwarp();

        // layer 3 (results stay in registers)
        float2 d0 = dot64(make_float2(S->B3[j],      S->B3[j + 32]),      bB,      S->W3[0], j);
        float2 d1 = dot64(make_float2(S->B3[64 + j], S->B3[96 + j]),      bB + 64, S->W3[1], j);
        float2 x3[2];
        x3[0] = make_float2(fmaxf(d0.x, 0.f), fmaxf(d0.y, 0.f));
        x3[1] = make_float2(fmaxf(d1.x, 0.f), fmaxf(d1.y, 0.f));

        // final layer: 2 outputs per type, warp-reduce; accurate tanhf (tiny outputs)
#pragma unroll
        for (int t = 0; t < 2; t++) {
            float2 m0 = *(const float2*)&S->W4[t][j * 2];
            float2 m1 = *(const float2*)&S->W4[t][(j + 32) * 2];
            float p0 = x3[t].x * m0.x + x3[t].y * m1.x;
            float p1 = x3[t].x * m0.y + x3[t].y * m1.y;
#pragma unroll
            for (int off = 16; off; off >>= 1) {
                p0 += __shfl_xor_sync(0xffffffffu, p0, off);
                p1 += __shfl_xor_sync(0xffffffffu, p1, off);
            }
            float o0 = tanhf(p0 + S->B4[t * 2 + 0]);
            float o1 = tanhf(p1 + S->B4[t * 2 + 1]);
            if (t == 0) {
                if (j < 5) *(float2*)&out[(size_t)g * 12 + j * 2] = make_float2(o0, o1);
            } else {
                if (j == 0) *(float2*)&out[(size_t)g * 12 + 10] = make_float2(o0, o1);
            }
        }
        __syncwarp();
    }
}

// ---------------------------------------------------------------------------
extern "C" void kernel_launch(void* const* d_in, const int* in_sizes, int n_in,
                              void* d_out, int out_size) {
    const float* obs = (const float*)d_in[0];
    const float* Wp1 = (const float*)d_in[1];
    const float* bp1 = (const float*)d_in[2];
    const float* Ws1 = (const float*)d_in[3];
    const float* Wn1 = (const float*)d_in[4];
    const float* b1  = (const float*)d_in[5];
    const float* Wp2 = (const float*)d_in[6];
    const float* bp2 = (const float*)d_in[7];
    const float* Ws2 = (const float*)d_in[8];
    const float* Wn2 = (const float*)d_in[9];
    const float* b2  = (const float*)d_in[10];
    const float* MW1 = (const float*)d_in[11];
    const float* Mb1 = (const float*)d_in[12];
    const float* MW2 = (const float*)d_in[13];
    const float* Mb2 = (const float*)d_in[14];
    const float* MW3 = (const float*)d_in[15];
    const float* Mb3 = (const float*)d_in[16];
    const float* MW4 = (const float*)d_in[17];
    const float* Mb4 = (const float*)d_in[18];
    float* out = (float*)d_out;

    const int G = in_sizes[0] / 384;

    cudaFuncSetAttribute(conv_kernel, cudaFuncAttributeMaxDynamicSharedMemorySize,
                         (int)sizeof(SmemConv));
    cudaFuncSetAttribute(mlp_kernel, cudaFuncAttributeMaxDynamicSharedMemorySize,
                         (int)sizeof(SmemMlp));

    conv_kernel<<<296, 256, sizeof(SmemConv)>>>(obs, Wp1, bp1, Ws1, Wn1, b1,
                                                Wp2, bp2, Ws2, Wn2, b2, G);
    mlp_kernel<<<296, 256, sizeof(SmemMlp)>>>(MW1, Mb1, MW2, Mb2, MW3, Mb3,
                                              MW4, Mb4, out, G);
}

// round 3
// speedup vs baseline: 1.7587x; 1.7587x over previous
#include <cuda_runtime.h>
#include <math.h>

typedef unsigned long long u64;
#define DEVFN __device__ __forceinline__

constexpr int G_MAX = 131072;
__device__ float g_res[(size_t)G_MAX * 64];

// ---------------------------------------------------------------------------
// f32x2 packed helpers
// ---------------------------------------------------------------------------
DEVFN u64 packf2(float lo, float hi) {
    u64 r; asm("mov.b64 %0, {%1, %2};" : "=l"(r) : "f"(lo), "f"(hi)); return r;
}
DEVFN u64 pack2(float x) { return packf2(x, x); }
DEVFN float2 unpk(u64 v) {
    float lo, hi; asm("mov.b64 {%0, %1}, %2;" : "=f"(lo), "=f"(hi) : "l"(v));
    return make_float2(lo, hi);
}
DEVFN u64 ffma2(u64 a, u64 b, u64 c) {
    u64 d; asm("fma.rn.f32x2 %0, %1, %2, %3;" : "=l"(d) : "l"(a), "l"(b), "l"(c));
    return d;
}
DEVFN u64 fadd2(u64 a, u64 b) {
    u64 d; asm("add.rn.f32x2 %0, %1, %2;" : "=l"(d) : "l"(a), "l"(b)); return d;
}

// tanh via exp2 + rcp approx (~1e-6 rel for O(1) args); used only for conv hidden.
DEVFN float ftanh(float x) {
    float e; asm("ex2.approx.f32 %0, %1;" : "=f"(e) : "f"(x * 2.885390081777927f));
    float r; asm("rcp.approx.f32 %0, %1;" : "=f"(r) : "f"(e + 1.0f));
    return fmaf(-2.0f, r, 1.0f);
}

// ---------------------------------------------------------------------------
// Packed-tile GEMM pass.
// P layout: float4 P[p][k2] = {x[2p][2k2], x[2p+1][2k2], x[2p][2k2+1], x[2p+1][2k2+1]}
// W layout: float2 W[k*32 + j] = {W[k][j], W[k][j+32]}
// acc[p][c] (u64) = packed results for rows (2p, 2p+1), column c in {j, j+32}.
// ---------------------------------------------------------------------------
template<int NP>
DEVFN void pass_gemm(u64 (&acc)[NP][2], const float4* __restrict__ P,
                     const float2* __restrict__ W, int j) {
    const ulonglong2* __restrict__ P2 = reinterpret_cast<const ulonglong2*>(P);
#pragma unroll 4
    for (int k2 = 0; k2 < 32; k2++) {
        float2 wa = W[(2 * k2) * 32 + j];
        float2 wb = W[(2 * k2 + 1) * 32 + j];
        u64 A0 = pack2(wa.x), A1 = pack2(wa.y);
        u64 B0 = pack2(wb.x), B1 = pack2(wb.y);
#pragma unroll
        for (int p = 0; p < NP; p++) {
            ulonglong2 X = P2[p * 32 + k2];     // broadcast LDS.128
            acc[p][0] = ffma2(X.x, A0, acc[p][0]);
            acc[p][1] = ffma2(X.x, A1, acc[p][1]);
            acc[p][0] = ffma2(X.y, B0, acc[p][0]);
            acc[p][1] = ffma2(X.y, B1, acc[p][1]);
        }
    }
}

DEVFN void stage_pairs(float2* dst, const float* __restrict__ src, int tid, int nt) {
    for (int idx = tid; idx < 2048; idx += nt) {
        int k = idx >> 5, j = idx & 31;
        dst[idx] = make_float2(src[k * 64 + j], src[k * 64 + j + 32]);
    }
}

// ---------------------------------------------------------------------------
// Shared-memory layouts (single block per SM)
// ---------------------------------------------------------------------------
struct SmemConv {
    float2 Wp1[2048], Ws1[2048], Wn1[2048];
    float2 Wp2[2048], Ws2[2048], Wn2[2048];       // 98304 B
    float  bp1[64], b1[64], bp2[64], b2[64];      //  1024 B
    float4 xsp[16][12 * 32];                      // 98304 B : 24 rows packed per warp
    float4 axp[16][2 * 32];                       // 16384 B : 4 rows packed per warp
};                                                // 214016 B

struct SmemMlp {
    float2 W[6][2048];                            // [layer*2+type]   98304 B
    float  W4[2][128];                            //  1024 B
    float  B1[128], B2[128], B3[128], B4[4];      //  1552 B
    float4 rsp[16][4 * 32];                       // 32768 B : 8 rows packed per warp
    float4 bufA[16][4 * 32];                      // 32768 B
    float4 bufB[16][4 * 32];                      // 32768 B
};                                                // ~199184 B

// element (row r, col c) of a packed tile lives at float index:
//   (( (r>>1)*32 + (c>>1) ) * 4) + 2*(c&1) + (r&1)

// ---------------------------------------------------------------------------
// Kernel 1: conv1 + conv2 + mean-pool -> g_res[G][64].  4 groups / warp pass.
// ---------------------------------------------------------------------------
__global__ void __launch_bounds__(512, 1)
conv_kernel(const float* __restrict__ obs,
            const float* __restrict__ Wp1, const float* __restrict__ bp1,
            const float* __restrict__ Ws1, const float* __restrict__ Wn1,
            const float* __restrict__ b1,
            const float* __restrict__ Wp2, const float* __restrict__ bp2,
            const float* __restrict__ Ws2, const float* __restrict__ Wn2,
            const float* __restrict__ b2,
            int G)
{
    extern __shared__ char sraw[];
    SmemConv* S = (SmemConv*)sraw;
    const int tid = threadIdx.x;

    stage_pairs(S->Wp1, Wp1, tid, 512);
    stage_pairs(S->Ws1, Ws1, tid, 512);
    stage_pairs(S->Wn1, Wn1, tid, 512);
    stage_pairs(S->Wp2, Wp2, tid, 512);
    stage_pairs(S->Ws2, Ws2, tid, 512);
    stage_pairs(S->Wn2, Wn2, tid, 512);
    if (tid < 64) {
        S->bp1[tid] = bp1[tid]; S->b1[tid] = b1[tid];
        S->bp2[tid] = bp2[tid]; S->b2[tid] = b2[tid];
    }
    __syncthreads();

    const int wid = tid >> 5, j = tid & 31;
    float4* xsp = S->xsp[wid];
    float4* axp = S->axp[wid];
    float*  xsf = (float*)xsp;
    float*  axf = (float*)axp;
    const float2* obs2 = (const float2*)obs;

    const int NQ = (G + 3) >> 2;
    const int lastrow = G * 6 - 1;

    for (int q = blockIdx.x * 16 + wid; q < NQ; q += gridDim.x * 16) {
        const int rowbase = q * 24;

        // ---- stage obs quad into packed layout ----
#pragma unroll
        for (int i = 0; i < 12; i++) {
            int ra = rowbase + 2 * i; if (ra > lastrow) ra = lastrow;
            int rb = ra + 1;          if (rb > lastrow) rb = lastrow;
            float2 a = obs2[(size_t)ra * 32 + j];
            float2 b = obs2[(size_t)rb * 32 + j];
            xsp[i * 32 + j] = make_float4(a.x, b.x, a.y, b.y);
        }
        __syncwarp();

        // ---- conv1 pool-proj ----
        u64 acc[12][2];
        {
            u64 d0 = pack2(S->bp1[j]), d1 = pack2(S->bp1[j + 32]);
#pragma unroll
            for (int p = 0; p < 12; p++) { acc[p][0] = d0; acc[p][1] = d1; }
        }
        pass_gemm<12>(acc, xsp, S->Wp1, j);

        // neigh = max over 6 rows (pairs 3g..3g+2), with relu clamp at 0
        float nbx[4], nby[4];
#pragma unroll
        for (int g = 0; g < 4; g++) {
            float mx = 0.f, my = 0.f;
#pragma unroll
            for (int p = 3 * g; p < 3 * g + 3; p++) {
                float2 c0 = unpk(acc[p][0]); float2 c1 = unpk(acc[p][1]);
                mx = fmaxf(mx, fmaxf(c0.x, c0.y));
                my = fmaxf(my, fmaxf(c1.x, c1.y));
            }
            nbx[g] = mx; nby[g] = my;
        }
#pragma unroll
        for (int g = 0; g < 4; g++) {
            axf[((g >> 1) * 32 + (j >> 1)) * 4 + 2 * (j & 1) + (g & 1)]        = nbx[g];
            axf[((g >> 1) * 32 + 16 + (j >> 1)) * 4 + 2 * (j & 1) + (g & 1)]   = nby[g];
        }
        __syncwarp();

        // nt = neigh @ Wn1 + b1
        u64 accN[2][2];
        accN[0][0] = accN[1][0] = pack2(S->b1[j]);
        accN[0][1] = accN[1][1] = pack2(S->b1[j + 32]);
        pass_gemm<2>(accN, axp, S->Wn1, j);
        float ntx[4], nty[4];
        {
            float2 a0 = unpk(accN[0][0]), a1 = unpk(accN[1][0]);
            ntx[0] = a0.x; ntx[1] = a0.y; ntx[2] = a1.x; ntx[3] = a1.y;
            float2 c0 = unpk(accN[0][1]), c1 = unpk(accN[1][1]);
            nty[0] = c0.x; nty[1] = c0.y; nty[2] = c1.x; nty[3] = c1.y;
        }

        // ---- conv1 self-proj ----
#pragma unroll
        for (int p = 0; p < 12; p++) { acc[p][0] = 0ull; acc[p][1] = 0ull; }
        pass_gemm<12>(acc, xsp, S->Ws1, j);
        __syncwarp();   // everyone done reading xsp(obs) before h1 overwrite

        // h1 = tanh(self + nt); write back packed; accumulate per-group row-sums
        float s1x[4] = {0, 0, 0, 0}, s1y[4] = {0, 0, 0, 0};
#pragma unroll
        for (int p = 0; p < 12; p++) {
            const int g = p / 3;
            float2 s0 = unpk(acc[p][0]);
            float h0 = ftanh(s0.x + ntx[g]);
            float h1v = ftanh(s0.y + ntx[g]);
            s1x[g] += h0 + h1v;
            *(u64*)&xsf[(p * 32 + (j >> 1)) * 4 + 2 * (j & 1)] = packf2(h0, h1v);
            float2 s1v = unpk(acc[p][1]);
            float h2 = ftanh(s1v.x + nty[g]);
            float h3 = ftanh(s1v.y + nty[g]);
            s1y[g] += h2 + h3;
            *(u64*)&xsf[(p * 32 + 16 + (j >> 1)) * 4 + 2 * (j & 1)] = packf2(h2, h3);
        }
#pragma unroll
        for (int g = 0; g < 4; g++) {
            axf[((g >> 1) * 32 + (j >> 1)) * 4 + 2 * (j & 1) + (g & 1)]        = s1x[g];
            axf[((g >> 1) * 32 + 16 + (j >> 1)) * 4 + 2 * (j & 1) + (g & 1)]   = s1y[g];
        }
        __syncwarp();

        // ss = s1 @ Ws2 (self-term collapsed under the mean)
        u64 accSS[2][2] = {{0ull, 0ull}, {0ull, 0ull}};
        pass_gemm<2>(accSS, axp, S->Ws2, j);
        float ssx[4], ssy[4];
        {
            float2 a0 = unpk(accSS[0][0]), a1 = unpk(accSS[1][0]);
            ssx[0] = a0.x; ssx[1] = a0.y; ssx[2] = a1.x; ssx[3] = a1.y;
            float2 c0 = unpk(accSS[0][1]), c1 = unpk(accSS[1][1]);
            ssy[0] = c0.x; ssy[1] = c0.y; ssy[2] = c1.x; ssy[3] = c1.y;
        }

        // ---- conv2 pool-proj on h1 ----
        {
            u64 d0 = pack2(S->bp2[j]), d1 = pack2(S->bp2[j + 32]);
#pragma unroll
            for (int p = 0; p < 12; p++) { acc[p][0] = d0; acc[p][1] = d1; }
        }
        pass_gemm<12>(acc, xsp, S->Wp2, j);
        float n2bx[4], n2by[4];
#pragma unroll
        for (int g = 0; g < 4; g++) {
            float mx = 0.f, my = 0.f;
#pragma unroll
            for (int p = 3 * g; p < 3 * g + 3; p++) {
                float2 c0 = unpk(acc[p][0]); float2 c1 = unpk(acc[p][1]);
                mx = fmaxf(mx, fmaxf(c0.x, c0.y));
                my = fmaxf(my, fmaxf(c1.x, c1.y));
            }
            n2bx[g] = mx; n2by[g] = my;
        }
        __syncwarp();   // accSS pass done reading axp
#pragma unroll
        for (int g = 0; g < 4; g++) {
            axf[((g >> 1) * 32 + (j >> 1)) * 4 + 2 * (j & 1) + (g & 1)]        = n2bx[g];
            axf[((g >> 1) * 32 + 16 + (j >> 1)) * 4 + 2 * (j & 1) + (g & 1)]   = n2by[g];
        }
        __syncwarp();

        // nt2 = neigh2 @ Wn2 + b2
        u64 accN2[2][2];
        accN2[0][0] = accN2[1][0] = pack2(S->b2[j]);
        accN2[0][1] = accN2[1][1] = pack2(S->b2[j + 32]);
        pass_gemm<2>(accN2, axp, S->Wn2, j);
        float n2x[4], n2y[4];
        {
            float2 a0 = unpk(accN2[0][0]), a1 = unpk(accN2[1][0]);
            n2x[0] = a0.x; n2x[1] = a0.y; n2x[2] = a1.x; n2x[3] = a1.y;
            float2 c0 = unpk(accN2[0][1]), c1 = unpk(accN2[1][1]);
            n2y[0] = c0.x; n2y[1] = c0.y; n2y[2] = c1.x; n2y[3] = c1.y;
        }

        // res = nt2 + ss/6
        const int gb = q * 4;
#pragma unroll
        for (int g = 0; g < 4; g++) {
            if (gb + g < G) {
                float* rg = g_res + (size_t)(gb + g) * 64;
                rg[j]      = fmaf(ssx[g], 1.0f / 6.0f, n2x[g]);
                rg[j + 32] = fmaf(ssy[g], 1.0f / 6.0f, n2y[g]);
            }
        }
        __syncwarp();
    }
}

// ---------------------------------------------------------------------------
// Kernel 2: per-type actor MLPs.  8 groups / warp pass, types sequential.
// ---------------------------------------------------------------------------
__global__ void __launch_bounds__(512, 1)
mlp_kernel(const float* __restrict__ MW1, const float* __restrict__ Mb1,
           const float* __restrict__ MW2, const float* __restrict__ Mb2,
           const float* __restrict__ MW3, const float* __restrict__ Mb3,
           const float* __restrict__ MW4, const float* __restrict__ Mb4,
           float* __restrict__ out, int G)
{
    extern __shared__ char sraw[];
    SmemMlp* S = (SmemMlp*)sraw;
    const int tid = threadIdx.x;

    stage_pairs(S->W[0], MW1,        tid, 512);
    stage_pairs(S->W[1], MW1 + 4096, tid, 512);
    stage_pairs(S->W[2], MW2,        tid, 512);
    stage_pairs(S->W[3], MW2 + 4096, tid, 512);
    stage_pairs(S->W[4], MW3,        tid, 512);
    stage_pairs(S->W[5], MW3 + 4096, tid, 512);
    if (tid < 256) ((float*)S->W4)[tid] = MW4[tid];
    if (tid < 128) { S->B1[tid] = Mb1[tid]; S->B2[tid] = Mb2[tid]; S->B3[tid] = Mb3[tid]; }
    if (tid < 4)   S->B4[tid] = Mb4[tid];
    __syncthreads();

    const int wid = tid >> 5, j = tid & 31;
    float4* rsp  = S->rsp[wid];
    float4* bAp  = S->bufA[wid];
    float4* bBp  = S->bufB[wid];
    float*  bAf  = (float*)bAp;
    float*  bBf  = (float*)bBp;
    const float2* r2 = (const float2*)g_res;

    const int NB = (G + 7) >> 3;
    const int lastg = G - 1;

    for (int b = blockIdx.x * 16 + wid; b < NB; b += gridDim.x * 16) {
        const int gb = b * 8;
#pragma unroll
        for (int i = 0; i < 4; i++) {
            int ga = gb + 2 * i; if (ga > lastg) ga = lastg;
            int gc = ga + 1;     if (gc > lastg) gc = lastg;
            float2 a = r2[(size_t)ga * 32 + j];
            float2 c = r2[(size_t)gc * 32 + j];
            rsp[i * 32 + j] = make_float4(a.x, c.x, a.y, c.y);
        }
        __syncwarp();

#pragma unroll
        for (int t = 0; t < 2; t++) {
            u64 acc[4][2];
            // layer 1: rsp -> bufA
            {
                u64 d0 = pack2(S->B1[t * 64 + j]), d1 = pack2(S->B1[t * 64 + j + 32]);
#pragma unroll
                for (int p = 0; p < 4; p++) { acc[p][0] = d0; acc[p][1] = d1; }
            }
            pass_gemm<4>(acc, rsp, S->W[t], j);
#pragma unroll
            for (int p = 0; p < 4; p++) {
                float2 c0 = unpk(acc[p][0]);
                *(u64*)&bAf[(p * 32 + (j >> 1)) * 4 + 2 * (j & 1)] =
                    packf2(fmaxf(c0.x, 0.f), fmaxf(c0.y, 0.f));
                float2 c1 = unpk(acc[p][1]);
                *(u64*)&bAf[(p * 32 + 16 + (j >> 1)) * 4 + 2 * (j & 1)] =
                    packf2(fmaxf(c1.x, 0.f), fmaxf(c1.y, 0.f));
            }
            __syncwarp();

            // layer 2: bufA -> bufB
            {
                u64 d0 = pack2(S->B2[t * 64 + j]), d1 = pack2(S->B2[t * 64 + j + 32]);
#pragma unroll
                for (int p = 0; p < 4; p++) { acc[p][0] = d0; acc[p][1] = d1; }
            }
            pass_gemm<4>(acc, bAp, S->W[2 + t], j);
#pragma unroll
            for (int p = 0; p < 4; p++) {
                float2 c0 = unpk(acc[p][0]);
                *(u64*)&bBf[(p * 32 + (j >> 1)) * 4 + 2 * (j & 1)] =
                    packf2(fmaxf(c0.x, 0.f), fmaxf(c0.y, 0.f));
                float2 c1 = unpk(acc[p][1]);
                *(u64*)&bBf[(p * 32 + 16 + (j >> 1)) * 4 + 2 * (j & 1)] =
                    packf2(fmaxf(c1.x, 0.f), fmaxf(c1.y, 0.f));
            }
            __syncwarp();

            // layer 3: bufB -> registers (relu'd)
            {
                u64 d0 = pack2(S->B3[t * 64 + j]), d1 = pack2(S->B3[t * 64 + j + 32]);
#pragma unroll
                for (int p = 0; p < 4; p++) { acc[p][0] = d0; acc[p][1] = d1; }
            }
            pass_gemm<4>(acc, bBp, S->W[4 + t], j);
            float xj[8], xj32[8];
#pragma unroll
            for (int p = 0; p < 4; p++) {
                float2 c0 = unpk(acc[p][0]);
                xj[2 * p] = fmaxf(c0.x, 0.f);  xj[2 * p + 1] = fmaxf(c0.y, 0.f);
                float2 c1 = unpk(acc[p][1]);
                xj32[2 * p] = fmaxf(c1.x, 0.f); xj32[2 * p + 1] = fmaxf(c1.y, 0.f);
            }

            // final layer: 2 outputs, warp-reduced; accurate tanhf (tiny outputs)
            float2 m0 = *(const float2*)&S->W4[t][j * 2];
            float2 m1 = *(const float2*)&S->W4[t][(j + 32) * 2];
            const float bo0 = S->B4[t * 2], bo1 = S->B4[t * 2 + 1];
#pragma unroll
            for (int g = 0; g < 8; g++) {
                float p0 = xj[g] * m0.x + xj32[g] * m1.x;
                float p1 = xj[g] * m0.y + xj32[g] * m1.y;
                u64 pk = packf2(p0, p1);
#pragma unroll
                for (int off = 16; off; off >>= 1)
                    pk = fadd2(pk, __shfl_xor_sync(0xffffffffu, pk, off));
                float2 o = unpk(pk);
                const bool valid = (gb + g) < G;
                if (t == 0) {
                    if (j < 5 && valid) {
                        float o0 = tanhf(o.x + bo0), o1 = tanhf(o.y + bo1);
                        *(float2*)&out[(size_t)(gb + g) * 12 + j * 2] = make_float2(o0, o1);
                    }
                } else {
                    if (j == 0 && valid) {
                        float o0 = tanhf(o.x + bo0), o1 = tanhf(o.y + bo1);
                        *(float2*)&out[(size_t)(gb + g) * 12 + 10] = make_float2(o0, o1);
                    }
                }
            }
            __syncwarp();   // before bufA overwrite by next type
        }
    }
}

// ---------------------------------------------------------------------------
extern "C" void kernel_launch(void* const* d_in, const int* in_sizes, int n_in,
                              void* d_out, int out_size) {
    const float* obs = (const float*)d_in[0];
    const float* Wp1 = (const float*)d_in[1];
    const float* bp1 = (const float*)d_in[2];
    const float* Ws1 = (const float*)d_in[3];
    const float* Wn1 = (const float*)d_in[4];
    const float* b1  = (const float*)d_in[5];
    const float* Wp2 = (const float*)d_in[6];
    const float* bp2 = (const float*)d_in[7];
    const float* Ws2 = (const float*)d_in[8];
    const float* Wn2 = (const float*)d_in[9];
    const float* b2  = (const float*)d_in[10];
    const float* MW1 = (const float*)d_in[11];
    const float* Mb1 = (const float*)d_in[12];
    const float* MW2 = (const float*)d_in[13];
    const float* Mb2 = (const float*)d_in[14];
    const float* MW3 = (const float*)d_in[15];
    const float* Mb3 = (const float*)d_in[16];
    const float* MW4 = (const float*)d_in[17];
    const float* Mb4 = (const float*)d_in[18];
    float* out = (float*)d_out;

    const int G = in_sizes[0] / 384;

    cudaFuncSetAttribute(conv_kernel, cudaFuncAttributeMaxDynamicSharedMemorySize,
                         (int)sizeof(SmemConv));
    cudaFuncSetAttribute(mlp_kernel, cudaFuncAttributeMaxDynamicSharedMemorySize,
                         (int)sizeof(SmemMlp));

    conv_kernel<<<148, 512, sizeof(SmemConv)>>>(obs, Wp1, bp1, Ws1, Wn1, b1,
                                                Wp2, bp2, Ws2, Wn2, b2, G);
    mlp_kernel<<<148, 512, sizeof(SmemMlp)>>>(MW1, Mb1, MW2, Mb2, MW3, Mb3,
                                              MW4, Mb4, out, G);
}

// round 7
// speedup vs baseline: 1.7599x; 1.0007x over previous
#include <cuda_runtime.h>
#include <math.h>

typedef unsigned long long u64;
#define DEVFN __device__ __forceinline__

constexpr int G_MAX = 131072;
__device__ float g_res[(size_t)G_MAX * 64];

// ---------------------------------------------------------------------------
// f32x2 packed helpers
// ---------------------------------------------------------------------------
DEVFN u64 packf2(float lo, float hi) {
    u64 r; asm("mov.b64 %0, {%1, %2};" : "=l"(r) : "f"(lo), "f"(hi)); return r;
}
DEVFN u64 pack2(float x) { return packf2(x, x); }
DEVFN float2 unpk(u64 v) {
    float lo, hi; asm("mov.b64 {%0, %1}, %2;" : "=f"(lo), "=f"(hi) : "l"(v));
    return make_float2(lo, hi);
}
DEVFN u64 ffma2(u64 a, u64 b, u64 c) {
    u64 d; asm("fma.rn.f32x2 %0, %1, %2, %3;" : "=l"(d) : "l"(a), "l"(b), "l"(c));
    return d;
}
DEVFN u64 fadd2(u64 a, u64 b) {
    u64 d; asm("add.rn.f32x2 %0, %1, %2;" : "=l"(d) : "l"(a), "l"(b)); return d;
}

// tanh via exp2 + rcp approx (~1e-6 rel for O(1) args); used only for conv hidden.
DEVFN float ftanh(float x) {
    float e; asm("ex2.approx.f32 %0, %1;" : "=f"(e) : "f"(x * 2.885390081777927f));
    float r; asm("rcp.approx.f32 %0, %1;" : "=f"(r) : "f"(e + 1.0f));
    return fmaf(-2.0f, r, 1.0f);
}

// ---------------------------------------------------------------------------
// Packed-tile GEMM pass.
// P layout: float4 P[p][k2] = {x[2p][2k2], x[2p+1][2k2], x[2p][2k2+1], x[2p+1][2k2+1]}
// W layout: float2 W[k*32 + j] = {W[k][j], W[k][j+32]}
// acc[p][c] (u64) = packed results for rows (2p, 2p+1), column c in {j, j+32}.
// ---------------------------------------------------------------------------
template<int NP>
DEVFN void pass_gemm(u64 (&acc)[NP][2], const float4* __restrict__ P,
                     const float2* __restrict__ W, int j) {
    const ulonglong2* __restrict__ P2 = reinterpret_cast<const ulonglong2*>(P);
#pragma unroll 4
    for (int k2 = 0; k2 < 32; k2++) {
        float2 wa = W[(2 * k2) * 32 + j];
        float2 wb = W[(2 * k2 + 1) * 32 + j];
        u64 A0 = pack2(wa.x), A1 = pack2(wa.y);
        u64 B0 = pack2(wb.x), B1 = pack2(wb.y);
#pragma unroll
        for (int p = 0; p < NP; p++) {
            ulonglong2 X = P2[p * 32 + k2];     // broadcast LDS.128
            acc[p][0] = ffma2(X.x, A0, acc[p][0]);
            acc[p][1] = ffma2(X.x, A1, acc[p][1]);
            acc[p][0] = ffma2(X.y, B0, acc[p][0]);
            acc[p][1] = ffma2(X.y, B1, acc[p][1]);
        }
    }
}

DEVFN void stage_pairs(float2* dst, const float* __restrict__ src, int tid, int nt) {
    for (int idx = tid; idx < 2048; idx += nt) {
        int k = idx >> 5, j = idx & 31;
        dst[idx] = make_float2(src[k * 64 + j], src[k * 64 + j + 32]);
    }
}

// ---------------------------------------------------------------------------
// Shared-memory layouts (single block per SM)
// ---------------------------------------------------------------------------
struct SmemConv {
    float2 Wp1[2048], Ws1[2048], Wn1[2048];
    float2 Wp2[2048], Ws2[2048], Wn2[2048];       // 98304 B
    float  bp1[64], b1[64], bp2[64], b2[64];      //  1024 B
    float4 xsp[16][12 * 32];                      // 98304 B : 24 rows packed per warp
    float4 axp[16][2 * 32];                       // 16384 B : 4 rows packed per warp
};                                                // 214016 B

struct SmemMlp {
    float2 W[6][2048];                            // [layer*2+type]   98304 B
    float  W4[2][128];                            //  1024 B
    float  B1[128], B2[128], B3[128], B4[4];      //  1552 B
    float4 rsp[16][4 * 32];                       // 32768 B : 8 rows packed per warp
    float4 bufA[16][4 * 32];                      // 32768 B
    float4 bufB[16][4 * 32];                      // 32768 B
};                                                // ~199184 B

// element (row r, col c) of a packed tile lives at float index:
//   (( (r>>1)*32 + (c>>1) ) * 4) + 2*(c&1) + (r&1)

// ---------------------------------------------------------------------------
// Kernel 1: conv1 + conv2 + mean-pool -> g_res[G][64].  4 groups / warp pass.
// ---------------------------------------------------------------------------
__global__ void __launch_bounds__(512, 1)
conv_kernel(const float* __restrict__ obs,
            const float* __restrict__ Wp1, const float* __restrict__ bp1,
            const float* __restrict__ Ws1, const float* __restrict__ Wn1,
            const float* __restrict__ b1,
            const float* __restrict__ Wp2, const float* __restrict__ bp2,
            const float* __restrict__ Ws2, const float* __restrict__ Wn2,
            const float* __restrict__ b2,
            int G)
{
    extern __shared__ char sraw[];
    SmemConv* S = (SmemConv*)sraw;
    const int tid = threadIdx.x;

    stage_pairs(S->Wp1, Wp1, tid, 512);
    stage_pairs(S->Ws1, Ws1, tid, 512);
    stage_pairs(S->Wn1, Wn1, tid, 512);
    stage_pairs(S->Wp2, Wp2, tid, 512);
    stage_pairs(S->Ws2, Ws2, tid, 512);
    stage_pairs(S->Wn2, Wn2, tid, 512);
    if (tid < 64) {
        S->bp1[tid] = bp1[tid]; S->b1[tid] = b1[tid];
        S->bp2[tid] = bp2[tid]; S->b2[tid] = b2[tid];
    }
    __syncthreads();

    const int wid = tid >> 5, j = tid & 31;
    float4* xsp = S->xsp[wid];
    float4* axp = S->axp[wid];
    float*  xsf = (float*)xsp;
    float*  axf = (float*)axp;
    const float2* obs2 = (const float2*)obs;

    const int NQ = (G + 3) >> 2;
    const int lastrow = G * 6 - 1;

    for (int q = blockIdx.x * 16 + wid; q < NQ; q += gridDim.x * 16) {
        const int rowbase = q * 24;

        // ---- stage obs quad into packed layout ----
#pragma unroll
        for (int i = 0; i < 12; i++) {
            int ra = rowbase + 2 * i; if (ra > lastrow) ra = lastrow;
            int rb = ra + 1;          if (rb > lastrow) rb = lastrow;
            float2 a = obs2[(size_t)ra * 32 + j];
            float2 b = obs2[(size_t)rb * 32 + j];
            xsp[i * 32 + j] = make_float4(a.x, b.x, a.y, b.y);
        }
        __syncwarp();

        // ---- conv1 pool-proj ----
        u64 acc[12][2];
        {
            u64 d0 = pack2(S->bp1[j]), d1 = pack2(S->bp1[j + 32]);
#pragma unroll
            for (int p = 0; p < 12; p++) { acc[p][0] = d0; acc[p][1] = d1; }
        }
        pass_gemm<12>(acc, xsp, S->Wp1, j);

        // neigh = max over 6 rows (pairs 3g..3g+2), with relu clamp at 0
        float nbx[4], nby[4];
#pragma unroll
        for (int g = 0; g < 4; g++) {
            float mx = 0.f, my = 0.f;
#pragma unroll
            for (int p = 3 * g; p < 3 * g + 3; p++) {
                float2 c0 = unpk(acc[p][0]); float2 c1 = unpk(acc[p][1]);
                mx = fmaxf(mx, fmaxf(c0.x, c0.y));
                my = fmaxf(my, fmaxf(c1.x, c1.y));
            }
            nbx[g] = mx; nby[g] = my;
        }
#pragma unroll
        for (int g = 0; g < 4; g++) {
            axf[((g >> 1) * 32 + (j >> 1)) * 4 + 2 * (j & 1) + (g & 1)]        = nbx[g];
            axf[((g >> 1) * 32 + 16 + (j >> 1)) * 4 + 2 * (j & 1) + (g & 1)]   = nby[g];
        }
        __syncwarp();

        // nt = neigh @ Wn1 + b1
        u64 accN[2][2];
        accN[0][0] = accN[1][0] = pack2(S->b1[j]);
        accN[0][1] = accN[1][1] = pack2(S->b1[j + 32]);
        pass_gemm<2>(accN, axp, S->Wn1, j);
        float ntx[4], nty[4];
        {
            float2 a0 = unpk(accN[0][0]), a1 = unpk(accN[1][0]);
            ntx[0] = a0.x; ntx[1] = a0.y; ntx[2] = a1.x; ntx[3] = a1.y;
            float2 c0 = unpk(accN[0][1]), c1 = unpk(accN[1][1]);
            nty[0] = c0.x; nty[1] = c0.y; nty[2] = c1.x; nty[3] = c1.y;
        }

        // ---- conv1 self-proj ----
#pragma unroll
        for (int p = 0; p < 12; p++) { acc[p][0] = 0ull; acc[p][1] = 0ull; }
        pass_gemm<12>(acc, xsp, S->Ws1, j);
        __syncwarp();   // everyone done reading xsp(obs) before h1 overwrite

        // h1 = tanh(self + nt); write back packed; accumulate per-group row-sums
        float s1x[4] = {0, 0, 0, 0}, s1y[4] = {0, 0, 0, 0};
#pragma unroll
        for (int p = 0; p < 12; p++) {
            const int g = p / 3;
            float2 s0 = unpk(acc[p][0]);
            float h0 = ftanh(s0.x + ntx[g]);
            float h1v = ftanh(s0.y + ntx[g]);
            s1x[g] += h0 + h1v;
            *(u64*)&xsf[(p * 32 + (j >> 1)) * 4 + 2 * (j & 1)] = packf2(h0, h1v);
            float2 s1v = unpk(acc[p][1]);
            float h2 = ftanh(s1v.x + nty[g]);
            float h3 = ftanh(s1v.y + nty[g]);
            s1y[g] += h2 + h3;
            *(u64*)&xsf[(p * 32 + 16 + (j >> 1)) * 4 + 2 * (j & 1)] = packf2(h2, h3);
        }
#pragma unroll
        for (int g = 0; g < 4; g++) {
            axf[((g >> 1) * 32 + (j >> 1)) * 4 + 2 * (j & 1) + (g & 1)]        = s1x[g];
            axf[((g >> 1) * 32 + 16 + (j >> 1)) * 4 + 2 * (j & 1) + (g & 1)]   = s1y[g];
        }
        __syncwarp();

        // ss = s1 @ Ws2 (self-term collapsed under the mean)
        u64 accSS[2][2] = {{0ull, 0ull}, {0ull, 0ull}};
        pass_gemm<2>(accSS, axp, S->Ws2, j);
        float ssx[4], ssy[4];
        {
            float2 a0 = unpk(accSS[0][0]), a1 = unpk(accSS[1][0]);
            ssx[0] = a0.x; ssx[1] = a0.y; ssx[2] = a1.x; ssx[3] = a1.y;
            float2 c0 = unpk(accSS[0][1]), c1 = unpk(accSS[1][1]);
            ssy[0] = c0.x; ssy[1] = c0.y; ssy[2] = c1.x; ssy[3] = c1.y;
        }

        // ---- conv2 pool-proj on h1 ----
        {
            u64 d0 = pack2(S->bp2[j]), d1 = pack2(S->bp2[j + 32]);
#pragma unroll
            for (int p = 0; p < 12; p++) { acc[p][0] = d0; acc[p][1] = d1; }
        }
        pass_gemm<12>(acc, xsp, S->Wp2, j);
        float n2bx[4], n2by[4];
#pragma unroll
        for (int g = 0; g < 4; g++) {
            float mx = 0.f, my = 0.f;
#pragma unroll
            for (int p = 3 * g; p < 3 * g + 3; p++) {
                float2 c0 = unpk(acc[p][0]); float2 c1 = unpk(acc[p][1]);
                mx = fmaxf(mx, fmaxf(c0.x, c0.y));
                my = fmaxf(my, fmaxf(c1.x, c1.y));
            }
            n2bx[g] = mx; n2by[g] = my;
        }
        __syncwarp();   // accSS pass done reading axp
#pragma unroll
        for (int g = 0; g < 4; g++) {
            axf[((g >> 1) * 32 + (j >> 1)) * 4 + 2 * (j & 1) + (g & 1)]        = n2bx[g];
            axf[((g >> 1) * 32 + 16 + (j >> 1)) * 4 + 2 * (j & 1) + (g & 1)]   = n2by[g];
        }
        __syncwarp();

        // nt2 = neigh2 @ Wn2 + b2
        u64 accN2[2][2];
        accN2[0][0] = accN2[1][0] = pack2(S->b2[j]);
        accN2[0][1] = accN2[1][1] = pack2(S->b2[j + 32]);
        pass_gemm<2>(accN2, axp, S->Wn2, j);
        float n2x[4], n2y[4];
        {
            float2 a0 = unpk(accN2[0][0]), a1 = unpk(accN2[1][0]);
            n2x[0] = a0.x; n2x[1] = a0.y; n2x[2] = a1.x; n2x[3] = a1.y;
            float2 c0 = unpk(accN2[0][1]), c1 = unpk(accN2[1][1]);
            n2y[0] = c0.x; n2y[1] = c0.y; n2y[2] = c1.x; n2y[3] = c1.y;
        }

        // res = nt2 + ss/6
        const int gb = q * 4;
#pragma unroll
        for (int g = 0; g < 4; g++) {
            if (gb + g < G) {
                float* rg = g_res + (size_t)(gb + g) * 64;
                rg[j]      = fmaf(ssx[g], 1.0f / 6.0f, n2x[g]);
                rg[j + 32] = fmaf(ssy[g], 1.0f / 6.0f, n2y[g]);
            }
        }
        __syncwarp();
    }
}

// ---------------------------------------------------------------------------
// Kernel 2: per-type actor MLPs.  8 groups / warp pass, types sequential.
// ---------------------------------------------------------------------------
__global__ void __launch_bounds__(512, 1)
mlp_kernel(const float* __restrict__ MW1, const float* __restrict__ Mb1,
           const float* __restrict__ MW2, const float* __restrict__ Mb2,
           const float* __restrict__ MW3, const float* __restrict__ Mb3,
           const float* __restrict__ MW4, const float* __restrict__ Mb4,
           float* __restrict__ out, int G)
{
    extern __shared__ char sraw[];
    SmemMlp* S = (SmemMlp*)sraw;
    const int tid = threadIdx.x;

    stage_pairs(S->W[0], MW1,        tid, 512);
    stage_pairs(S->W[1], MW1 + 4096, tid, 512);
    stage_pairs(S->W[2], MW2,        tid, 512);
    stage_pairs(S->W[3], MW2 + 4096, tid, 512);
    stage_pairs(S->W[4], MW3,        tid, 512);
    stage_pairs(S->W[5], MW3 + 4096, tid, 512);
    if (tid < 256) ((float*)S->W4)[tid] = MW4[tid];
    if (tid < 128) { S->B1[tid] = Mb1[tid]; S->B2[tid] = Mb2[tid]; S->B3[tid] = Mb3[tid]; }
    if (tid < 4)   S->B4[tid] = Mb4[tid];
    __syncthreads();

    const int wid = tid >> 5, j = tid & 31;
    float4* rsp  = S->rsp[wid];
    float4* bAp  = S->bufA[wid];
    float4* bBp  = S->bufB[wid];
    float*  bAf  = (float*)bAp;
    float*  bBf  = (float*)bBp;
    const float2* r2 = (const float2*)g_res;

    const int NB = (G + 7) >> 3;
    const int lastg = G - 1;

    for (int b = blockIdx.x * 16 + wid; b < NB; b += gridDim.x * 16) {
        const int gb = b * 8;
#pragma unroll
        for (int i = 0; i < 4; i++) {
            int ga = gb + 2 * i; if (ga > lastg) ga = lastg;
            int gc = ga + 1;     if (gc > lastg) gc = lastg;
            float2 a = r2[(size_t)ga * 32 + j];
            float2 c = r2[(size_t)gc * 32 + j];
            rsp[i * 32 + j] = make_float4(a.x, c.x, a.y, c.y);
        }
        __syncwarp();

#pragma unroll
        for (int t = 0; t < 2; t++) {
            u64 acc[4][2];
            // layer 1: rsp -> bufA
            {
                u64 d0 = pack2(S->B1[t * 64 + j]), d1 = pack2(S->B1[t * 64 + j + 32]);
#pragma unroll
                for (int p = 0; p < 4; p++) { acc[p][0] = d0; acc[p][1] = d1; }
            }
            pass_gemm<4>(acc, rsp, S->W[t], j);
#pragma unroll
            for (int p = 0; p < 4; p++) {
                float2 c0 = unpk(acc[p][0]);
                *(u64*)&bAf[(p * 32 + (j >> 1)) * 4 + 2 * (j & 1)] =
                    packf2(fmaxf(c0.x, 0.f), fmaxf(c0.y, 0.f));
                float2 c1 = unpk(acc[p][1]);
                *(u64*)&bAf[(p * 32 + 16 + (j >> 1)) * 4 + 2 * (j & 1)] =
                    packf2(fmaxf(c1.x, 0.f), fmaxf(c1.y, 0.f));
            }
            __syncwarp();

            // layer 2: bufA -> bufB
            {
                u64 d0 = pack2(S->B2[t * 64 + j]), d1 = pack2(S->B2[t * 64 + j + 32]);
#pragma unroll
                for (int p = 0; p < 4; p++) { acc[p][0] = d0; acc[p][1] = d1; }
            }
            pass_gemm<4>(acc, bAp, S->W[2 + t], j);
#pragma unroll
            for (int p = 0; p < 4; p++) {
                float2 c0 = unpk(acc[p][0]);
                *(u64*)&bBf[(p * 32 + (j >> 1)) * 4 + 2 * (j & 1)] =
                    packf2(fmaxf(c0.x, 0.f), fmaxf(c0.y, 0.f));
                float2 c1 = unpk(acc[p][1]);
                *(u64*)&bBf[(p * 32 + 16 + (j >> 1)) * 4 + 2 * (j & 1)] =
                    packf2(fmaxf(c1.x, 0.f), fmaxf(c1.y, 0.f));
            }
            __syncwarp();

            // layer 3: bufB -> registers (relu'd)
            {
                u64 d0 = pack2(S->B3[t * 64 + j]), d1 = pack2(S->B3[t * 64 + j + 32]);
#pragma unroll
                for (int p = 0; p < 4; p++) { acc[p][0] = d0; acc[p][1] = d1; }
            }
            pass_gemm<4>(acc, bBp, S->W[4 + t], j);
            float xj[8], xj32[8];
#pragma unroll
            for (int p = 0; p < 4; p++) {
                float2 c0 = unpk(acc[p][0]);
                xj[2 * p] = fmaxf(c0.x, 0.f);  xj[2 * p + 1] = fmaxf(c0.y, 0.f);
                float2 c1 = unpk(acc[p][1]);
                xj32[2 * p] = fmaxf(c1.x, 0.f); xj32[2 * p + 1] = fmaxf(c1.y, 0.f);
            }

            // final layer: 2 outputs, warp-reduced; accurate tanhf (tiny outputs)
            float2 m0 = *(const float2*)&S->W4[t][j * 2];
            float2 m1 = *(const float2*)&S->W4[t][(j + 32) * 2];
            const float bo0 = S->B4[t * 2], bo1 = S->B4[t * 2 + 1];
#pragma unroll
            for (int g = 0; g < 8; g++) {
                float p0 = xj[g] * m0.x + xj32[g] * m1.x;
                float p1 = xj[g] * m0.y + xj32[g] * m1.y;
                u64 pk = packf2(p0, p1);
#pragma unroll
                for (int off = 16; off; off >>= 1)
                    pk = fadd2(pk, __shfl_xor_sync(0xffffffffu, pk, off));
                float2 o = unpk(pk);
                const bool valid = (gb + g) < G;
                if (t == 0) {
                    if (j < 5 && valid) {
                        float o0 = tanhf(o.x + bo0), o1 = tanhf(o.y + bo1);
                        *(float2*)&out[(size_t)(gb + g) * 12 + j * 2] = make_float2(o0, o1);
                    }
                } else {
                    if (j == 0 && valid) {
                        float o0 = tanhf(o.x + bo0), o1 = tanhf(o.y + bo1);
                        *(float2*)&out[(size_t)(gb + g) * 12 + 10] = make_float2(o0, o1);
                    }
                }
            }
            __syncwarp();   // before bufA overwrite by next type
        }
    }
}

// ---------------------------------------------------------------------------
extern "C" void kernel_launch(void* const* d_in, const int* in_sizes, int n_in,
                              void* d_out, int out_size) {
    const float* obs = (const float*)d_in[0];
    const float* Wp1 = (const float*)d_in[1];
    const float* bp1 = (const float*)d_in[2];
    const float* Ws1 = (const float*)d_in[3];
    const float* Wn1 = (const float*)d_in[4];
    const float* b1  = (const float*)d_in[5];
    const float* Wp2 = (const float*)d_in[6];
    const float* bp2 = (const float*)d_in[7];
    const float* Ws2 = (const float*)d_in[8];
    const float* Wn2 = (const float*)d_in[9];
    const float* b2  = (const float*)d_in[10];
    const float* MW1 = (const float*)d_in[11];
    const float* Mb1 = (const float*)d_in[12];
    const float* MW2 = (const float*)d_in[13];
    const float* Mb2 = (const float*)d_in[14];
    const float* MW3 = (const float*)d_in[15];
    const float* Mb3 = (const float*)d_in[16];
    const float* MW4 = (const float*)d_in[17];
    const float* Mb4 = (const float*)d_in[18];
    float* out = (float*)d_out;

    const int G = in_sizes[0] / 384;

    cudaFuncSetAttribute(conv_kernel, cudaFuncAttributeMaxDynamicSharedMemorySize,
                         (int)sizeof(SmemConv));
    cudaFuncSetAttribute(mlp_kernel, cudaFuncAttributeMaxDynamicSharedMemorySize,
                         (int)sizeof(SmemMlp));

    conv_kernel<<<148, 512, sizeof(SmemConv)>>>(obs, Wp1, bp1, Ws1, Wn1, b1,
                                                Wp2, bp2, Ws2, Wn2, b2, G);
    mlp_kernel<<<148, 512, sizeof(SmemMlp)>>>(MW1, Mb1, MW2, Mb2, MW3, Mb3,
                                              MW4, Mb4, out, G);
}

// round 8
// speedup vs baseline: 1.8412x; 1.0462x over previous
#include <cuda_runtime.h>
#include <math.h>

typedef unsigned long long u64;
#define DEVFN __device__ __forceinline__

constexpr int G_MAX = 131072;
__device__ float g_res[(size_t)G_MAX * 64];

// ---------------------------------------------------------------------------
// f32x2 packed helpers
// ---------------------------------------------------------------------------
DEVFN u64 packf2(float lo, float hi) {
    u64 r; asm("mov.b64 %0, {%1, %2};" : "=l"(r) : "f"(lo), "f"(hi)); return r;
}
DEVFN u64 pack2(float x) { return packf2(x, x); }
DEVFN float2 unpk(u64 v) {
    float lo, hi; asm("mov.b64 {%0, %1}, %2;" : "=f"(lo), "=f"(hi) : "l"(v));
    return make_float2(lo, hi);
}
DEVFN u64 ffma2(u64 a, u64 b, u64 c) {
    u64 d; asm("fma.rn.f32x2 %0, %1, %2, %3;" : "=l"(d) : "l"(a), "l"(b), "l"(c));
    return d;
}
DEVFN u64 fadd2(u64 a, u64 b) {
    u64 d; asm("add.rn.f32x2 %0, %1, %2;" : "=l"(d) : "l"(a), "l"(b)); return d;
}
DEVFN float ftanh(float x) {
    float e; asm("ex2.approx.f32 %0, %1;" : "=f"(e) : "f"(x * 2.885390081777927f));
    float r; asm("rcp.approx.f32 %0, %1;" : "=f"(r) : "f"(e + 1.0f));
    return fmaf(-2.0f, r, 1.0f);
}

// ---------------------------------------------------------------------------
// Layouts.
// Activation tile (packed pairs): float4 P[p][k2] =
//   {x[2p][2k2], x[2p+1][2k2], x[2p][2k2+1], x[2p+1][2k2+1]}
//   element (row r, col c) at float index ((pair*32 + (c>>1))*4) + 2*(c&1) + (r&1)
// Weight quad: float4 Wq[k2*32 + j] = {W[2k2][j], W[2k2][j+32], W[2k2+1][j], W[2k2+1][j+32]}
// ---------------------------------------------------------------------------
DEVFN void stage_quads(float4* dst, const float* __restrict__ src, int tid, int nt) {
    for (int idx = tid; idx < 1024; idx += nt) {
        int k2 = idx >> 5, j = idx & 31;
        const float* r0 = src + (2 * k2) * 64;
        const float* r1 = src + (2 * k2 + 1) * 64;
        dst[idx] = make_float4(r0[j], r0[j + 32], r1[j], r1[j + 32]);
    }
}

// GEMM pass: acc[p][c] (u64) = packed rows (2p,2p+1), cols c in {j, j+32}.
template<int NP>
DEVFN void pass_gemm(u64 (&acc)[NP][2], const float4* __restrict__ P,
                     const float4* __restrict__ W, int j) {
    const ulonglong2* __restrict__ P2 = reinterpret_cast<const ulonglong2*>(P);
#pragma unroll 4
    for (int k2 = 0; k2 < 32; k2++) {
        float4 w = W[k2 * 32 + j];
        u64 A0 = pack2(w.x), A1 = pack2(w.y), B0 = pack2(w.z), B1 = pack2(w.w);
#pragma unroll
        for (int p = 0; p < NP; p++) {
            ulonglong2 X = P2[p * 32 + k2];
            acc[p][0] = ffma2(X.x, A0, acc[p][0]);
            acc[p][1] = ffma2(X.x, A1, acc[p][1]);
            acc[p][0] = ffma2(X.y, B0, acc[p][0]);
            acc[p][1] = ffma2(X.y, B1, acc[p][1]);
        }
    }
}

// Dual GEMM: same activations against two weight matrices (shares broadcasts).
template<int NP>
DEVFN void pass_gemm_dual(u64 (&aP)[NP][2], u64 (&aS)[NP][2],
                          const float4* __restrict__ P,
                          const float4* __restrict__ WP,
                          const float4* __restrict__ WS, int j) {
    const ulonglong2* __restrict__ P2 = reinterpret_cast<const ulonglong2*>(P);
#pragma unroll 2
    for (int k2 = 0; k2 < 32; k2++) {
        float4 wp = WP[k2 * 32 + j];
        float4 ws = WS[k2 * 32 + j];
        u64 Pa = pack2(wp.x), Pb = pack2(wp.y), Pc = pack2(wp.z), Pd = pack2(wp.w);
        u64 Sa = pack2(ws.x), Sb = pack2(ws.y), Sc = pack2(ws.z), Sd = pack2(ws.w);
#pragma unroll
        for (int p = 0; p < NP; p++) {
            ulonglong2 X = P2[p * 32 + k2];
            aP[p][0] = ffma2(X.x, Pa, aP[p][0]);
            aP[p][1] = ffma2(X.x, Pb, aP[p][1]);
            aP[p][0] = ffma2(X.y, Pc, aP[p][0]);
            aP[p][1] = ffma2(X.y, Pd, aP[p][1]);
            aS[p][0] = ffma2(X.x, Sa, aS[p][0]);
            aS[p][1] = ffma2(X.x, Sb, aS[p][1]);
            aS[p][0] = ffma2(X.y, Sc, aS[p][0]);
            aS[p][1] = ffma2(X.y, Sd, aS[p][1]);
        }
    }
}

// ---------------------------------------------------------------------------
// Shared-memory layouts (single 512-thread block per SM)
// ---------------------------------------------------------------------------
struct SmemConv {
    float4 Wp1[1024], Ws1[1024], Wn1[1024];
    float4 Wp2[1024], Ws2[1024], Wn2[1024];       //  98304 B
    float4 xsp[16][12 * 32];                      //  98304 B : 24 rows / warp
    float4 axp[16][4 * 32];                       //  32768 B : 8 aux rows / warp
    float  bp1[64], b1[64], bp2[64], b2[64];      //   1024 B
};                                                // 230400 B

struct SmemMlp {
    float4 W[6][1024];                            //  98304 B  [layer*2+type]
    float4 rsp[16][6 * 32];                       //  49152 B : 12 groups / warp
    float4 bufA[16][6 * 32];                      //  49152 B
    float  W4[2][128];                            //   1024 B
    float  B1[128], B2[128], B3[128], B4[4];      //   1552 B
};                                                // 199184 B

// ---------------------------------------------------------------------------
// Kernel 1: conv1 + conv2 + mean-pool -> g_res[G][64].  4 groups / warp pass.
// conv1 runs as fused (pool,self) dual pass in two 2-group chunks.
// ---------------------------------------------------------------------------
__global__ void __launch_bounds__(512, 1)
conv_kernel(const float* __restrict__ obs,
            const float* __restrict__ Wp1, const float* __restrict__ bp1,
            const float* __restrict__ Ws1, const float* __restrict__ Wn1,
            const float* __restrict__ b1,
            const float* __restrict__ Wp2, const float* __restrict__ bp2,
            const float* __restrict__ Ws2, const float* __restrict__ Wn2,
            const float* __restrict__ b2,
            int G)
{
    extern __shared__ char sraw[];
    SmemConv* S = (SmemConv*)sraw;
    const int tid = threadIdx.x;

    stage_quads(S->Wp1, Wp1, tid, 512);
    stage_quads(S->Ws1, Ws1, tid, 512);
    stage_quads(S->Wn1, Wn1, tid, 512);
    stage_quads(S->Wp2, Wp2, tid, 512);
    stage_quads(S->Ws2, Ws2, tid, 512);
    stage_quads(S->Wn2, Wn2, tid, 512);
    if (tid < 64) {
        S->bp1[tid] = bp1[tid]; S->b1[tid] = b1[tid];
        S->bp2[tid] = bp2[tid]; S->b2[tid] = b2[tid];
    }
    __syncthreads();

    const int wid = tid >> 5, j = tid & 31;
    float4* xsp = S->xsp[wid];
    float4* axp = S->axp[wid];
    float*  xsf = (float*)xsp;
    float*  axf = (float*)axp;
    const float2* obs2 = (const float2*)obs;

    const int NQ = (G + 3) >> 2;
    const int lastrow = G * 6 - 1;

    for (int q = blockIdx.x * 16 + wid; q < NQ; q += gridDim.x * 16) {
        const int rowbase = q * 24;

        // ---- stage obs quad (24 rows) into packed layout ----
#pragma unroll
        for (int i = 0; i < 12; i++) {
            int ra = rowbase + 2 * i; if (ra > lastrow) ra = lastrow;
            int rb = ra + 1;          if (rb > lastrow) rb = lastrow;
            float2 a = obs2[(size_t)ra * 32 + j];
            float2 b = obs2[(size_t)rb * 32 + j];
            xsp[i * 32 + j] = make_float4(a.x, b.x, a.y, b.y);
        }
        __syncwarp();

        // ---- conv1 in two 2-group chunks: fused pool+self dual pass ----
#pragma unroll
        for (int c = 0; c < 2; c++) {
            u64 aP[6][2], aS[6][2];
            {
                u64 d0 = pack2(S->bp1[j]), d1 = pack2(S->bp1[j + 32]);
#pragma unroll
                for (int p = 0; p < 6; p++) {
                    aP[p][0] = d0; aP[p][1] = d1;
                    aS[p][0] = 0ull; aS[p][1] = 0ull;
                }
            }
            pass_gemm_dual<6>(aP, aS, xsp + c * 6 * 32, S->Wp1, S->Ws1, j);

            // neigh = max over each group's 6 rows (3 pairs), relu-clamped
            float nbx[2], nby[2];
#pragma unroll
            for (int gg = 0; gg < 2; gg++) {
                float mx = 0.f, my = 0.f;
#pragma unroll
                for (int p = 3 * gg; p < 3 * gg + 3; p++) {
                    float2 c0 = unpk(aP[p][0]); float2 c1 = unpk(aP[p][1]);
                    mx = fmaxf(mx, fmaxf(c0.x, c0.y));
                    my = fmaxf(my, fmaxf(c1.x, c1.y));
                }
                nbx[gg] = mx; nby[gg] = my;
            }
#pragma unroll
            for (int gg = 0; gg < 2; gg++) {
                axf[(c * 32 + (j >> 1)) * 4 + 2 * (j & 1) + gg]      = nbx[gg];
                axf[(c * 32 + 16 + (j >> 1)) * 4 + 2 * (j & 1) + gg] = nby[gg];
            }
            __syncwarp();

            // nt = neigh @ Wn1 + b1 (1 packed pair = groups 2c, 2c+1)
            u64 aN[1][2];
            aN[0][0] = pack2(S->b1[j]); aN[0][1] = pack2(S->b1[j + 32]);
            pass_gemm<1>(aN, axp + c * 32, S->Wn1, j);
            float2 n0 = unpk(aN[0][0]);   // nt[g0..g1] at col j
            float2 n1 = unpk(aN[0][1]);   // at col j+32

            // h1 = tanh(self + nt) -> xsp (overwrite obs rows of this chunk)
            float s1x[2] = {0.f, 0.f}, s1y[2] = {0.f, 0.f};
#pragma unroll
            for (int p = 0; p < 6; p++) {
                const int gg = p / 3;
                const float ntxv = gg ? n0.y : n0.x;
                const float ntyv = gg ? n1.y : n1.x;
                float2 s0 = unpk(aS[p][0]);
                float h0 = ftanh(s0.x + ntxv);
                float h1v = ftanh(s0.y + ntxv);
                s1x[gg] += h0 + h1v;
                *(u64*)&xsf[((c * 6 + p) * 32 + (j >> 1)) * 4 + 2 * (j & 1)] =
                    packf2(h0, h1v);
                float2 s1v = unpk(aS[p][1]);
                float h2 = ftanh(s1v.x + ntyv);
                float h3 = ftanh(s1v.y + ntyv);
                s1y[gg] += h2 + h3;
                *(u64*)&xsf[((c * 6 + p) * 32 + 16 + (j >> 1)) * 4 + 2 * (j & 1)] =
                    packf2(h2, h3);
            }
            // s1 row-sums -> aux pairs 2,3
#pragma unroll
            for (int gg = 0; gg < 2; gg++) {
                axf[((2 + c) * 32 + (j >> 1)) * 4 + 2 * (j & 1) + gg]      = s1x[gg];
                axf[((2 + c) * 32 + 16 + (j >> 1)) * 4 + 2 * (j & 1) + gg] = s1y[gg];
            }
        }
        __syncwarp();

        // ss = s1 @ Ws2 (conv2 self-term collapsed under the mean)
        u64 aSS[2][2] = {{0ull, 0ull}, {0ull, 0ull}};
        pass_gemm<2>(aSS, axp + 2 * 32, S->Ws2, j);
        float ssx[4], ssy[4];
        {
            float2 a0 = unpk(aSS[0][0]), a1 = unpk(aSS[1][0]);
            ssx[0] = a0.x; ssx[1] = a0.y; ssx[2] = a1.x; ssx[3] = a1.y;
            float2 c0 = unpk(aSS[0][1]), c1 = unpk(aSS[1][1]);
            ssy[0] = c0.x; ssy[1] = c0.y; ssy[2] = c1.x; ssy[3] = c1.y;
        }

        // ---- conv2 pool-proj on h1 (all 4 groups) ----
        u64 acc[12][2];
        {
            u64 d0 = pack2(S->bp2[j]), d1 = pack2(S->bp2[j + 32]);
#pragma unroll
            for (int p = 0; p < 12; p++) { acc[p][0] = d0; acc[p][1] = d1; }
        }
        pass_gemm<12>(acc, xsp, S->Wp2, j);
        float n2bx[4], n2by[4];
#pragma unroll
        for (int g = 0; g < 4; g++) {
            float mx = 0.f, my = 0.f;
#pragma unroll
            for (int p = 3 * g; p < 3 * g + 3; p++) {
                float2 c0 = unpk(acc[p][0]); float2 c1 = unpk(acc[p][1]);
                mx = fmaxf(mx, fmaxf(c0.x, c0.y));
                my = fmaxf(my, fmaxf(c1.x, c1.y));
            }
            n2bx[g] = mx; n2by[g] = my;
        }
        __syncwarp();     // ss pass done reading aux pairs 2-3
#pragma unroll
        for (int g = 0; g < 4; g++) {
            axf[((g >> 1) * 32 + (j >> 1)) * 4 + 2 * (j & 1) + (g & 1)]      = n2bx[g];
            axf[((g >> 1) * 32 + 16 + (j >> 1)) * 4 + 2 * (j & 1) + (g & 1)] = n2by[g];
        }
        __syncwarp();

        // nt2 = neigh2 @ Wn2 + b2
        u64 aN2[2][2];
        aN2[0][0] = aN2[1][0] = pack2(S->b2[j]);
        aN2[0][1] = aN2[1][1] = pack2(S->b2[j + 32]);
        pass_gemm<2>(aN2, axp, S->Wn2, j);
        float n2x[4], n2y[4];
        {
            float2 a0 = unpk(aN2[0][0]), a1 = unpk(aN2[1][0]);
            n2x[0] = a0.x; n2x[1] = a0.y; n2x[2] = a1.x; n2x[3] = a1.y;
            float2 c0 = unpk(aN2[0][1]), c1 = unpk(aN2[1][1]);
            n2y[0] = c0.x; n2y[1] = c0.y; n2y[2] = c1.x; n2y[3] = c1.y;
        }

        // res = nt2 + ss/6
        const int gb = q * 4;
#pragma unroll
        for (int g = 0; g < 4; g++) {
            if (gb + g < G) {
                float* rg = g_res + (size_t)(gb + g) * 64;
                rg[j]      = fmaf(ssx[g], 1.0f / 6.0f, n2x[g]);
                rg[j + 32] = fmaf(ssy[g], 1.0f / 6.0f, n2y[g]);
            }
        }
        __syncwarp();     // all smem reads done before next quad restages
    }
}

// ---------------------------------------------------------------------------
// Kernel 2: per-type actor MLPs.  12 groups / warp pass, types sequential.
// Buffers ping-pong: rsp -> bufA -> rsp -> regs; rsp re-staged per type.
// ---------------------------------------------------------------------------
__global__ void __launch_bounds__(512, 1)
mlp_kernel(const float* __restrict__ MW1, const float* __restrict__ Mb1,
           const float* __restrict__ MW2, const float* __restrict__ Mb2,
           const float* __restrict__ MW3, const float* __restrict__ Mb3,
           const float* __restrict__ MW4, const float* __restrict__ Mb4,
           float* __restrict__ out, int G)
{
    extern __shared__ char sraw[];
    SmemMlp* S = (SmemMlp*)sraw;
    const int tid = threadIdx.x;

    stage_quads(S->W[0], MW1,        tid, 512);
    stage_quads(S->W[1], MW1 + 4096, tid, 512);
    stage_quads(S->W[2], MW2,        tid, 512);
    stage_quads(S->W[3], MW2 + 4096, tid, 512);
    stage_quads(S->W[4], MW3,        tid, 512);
    stage_quads(S->W[5], MW3 + 4096, tid, 512);
    if (tid < 256) ((float*)S->W4)[tid] = MW4[tid];
    if (tid < 128) { S->B1[tid] = Mb1[tid]; S->B2[tid] = Mb2[tid]; S->B3[tid] = Mb3[tid]; }
    if (tid < 4)   S->B4[tid] = Mb4[tid];
    __syncthreads();

    const int wid = tid >> 5, j = tid & 31;
    float4* rsp = S->rsp[wid];
    float4* bAp = S->bufA[wid];
    float*  rsf = (float*)rsp;
    float*  bAf = (float*)bAp;
    const float2* r2 = (const float2*)g_res;

    const int NB = (G + 11) / 12;
    const int lastg = G - 1;

    for (int b = blockIdx.x * 16 + wid; b < NB; b += gridDim.x * 16) {
        const int gb = b * 12;

#pragma unroll
        for (int t = 0; t < 2; t++) {
            // stage rsp (12 groups) — re-staged per type since layer 2 overwrites it
#pragma unroll
            for (int i = 0; i < 6; i++) {
                int ga = gb + 2 * i; if (ga > lastg) ga = lastg;
                int gc = ga + 1;     if (gc > lastg) gc = lastg;
                float2 a = r2[(size_t)ga * 32 + j];
                float2 c = r2[(size_t)gc * 32 + j];
                rsp[i * 32 + j] = make_float4(a.x, c.x, a.y, c.y);
            }
            __syncwarp();

            u64 acc[6][2];
            // layer 1: rsp -> bufA
            {
                u64 d0 = pack2(S->B1[t * 64 + j]), d1 = pack2(S->B1[t * 64 + j + 32]);
#pragma unroll
                for (int p = 0; p < 6; p++) { acc[p][0] = d0; acc[p][1] = d1; }
            }
            pass_gemm<6>(acc, rsp, S->W[t], j);
#pragma unroll
            for (int p = 0; p < 6; p++) {
                float2 c0 = unpk(acc[p][0]);
                *(u64*)&bAf[(p * 32 + (j >> 1)) * 4 + 2 * (j & 1)] =
                    packf2(fmaxf(c0.x, 0.f), fmaxf(c0.y, 0.f));
                float2 c1 = unpk(acc[p][1]);
                *(u64*)&bAf[(p * 32 + 16 + (j >> 1)) * 4 + 2 * (j & 1)] =
                    packf2(fmaxf(c1.x, 0.f), fmaxf(c1.y, 0.f));
            }
            __syncwarp();

            // layer 2: bufA -> rsp (overwrite)
            {
                u64 d0 = pack2(S->B2[t * 64 + j]), d1 = pack2(S->B2[t * 64 + j + 32]);
#pragma unroll
                for (int p = 0; p < 6; p++) { acc[p][0] = d0; acc[p][1] = d1; }
            }
            pass_gemm<6>(acc, bAp, S->W[2 + t], j);
#pragma unroll
            for (int p = 0; p < 6; p++) {
                float2 c0 = unpk(acc[p][0]);
                *(u64*)&rsf[(p * 32 + (j >> 1)) * 4 + 2 * (j & 1)] =
                    packf2(fmaxf(c0.x, 0.f), fmaxf(c0.y, 0.f));
                float2 c1 = unpk(acc[p][1]);
                *(u64*)&rsf[(p * 32 + 16 + (j >> 1)) * 4 + 2 * (j & 1)] =
                    packf2(fmaxf(c1.x, 0.f), fmaxf(c1.y, 0.f));
            }
            __syncwarp();

            // layer 3: rsp -> registers (relu'd)
            {
                u64 d0 = pack2(S->B3[t * 64 + j]), d1 = pack2(S->B3[t * 64 + j + 32]);
#pragma unroll
                for (int p = 0; p < 6; p++) { acc[p][0] = d0; acc[p][1] = d1; }
            }
            pass_gemm<6>(acc, rsp, S->W[4 + t], j);
            float xj[12], xj32[12];
#pragma unroll
            for (int p = 0; p < 6; p++) {
                float2 c0 = unpk(acc[p][0]);
                xj[2 * p] = fmaxf(c0.x, 0.f);  xj[2 * p + 1] = fmaxf(c0.y, 0.f);
                float2 c1 = unpk(acc[p][1]);
                xj32[2 * p] = fmaxf(c1.x, 0.f); xj32[2 * p + 1] = fmaxf(c1.y, 0.f);
            }

            // final layer: 2 outputs, warp-reduced; accurate tanhf (tiny outputs)
            float2 m0 = *(const float2*)&S->W4[t][j * 2];
            float2 m1 = *(const float2*)&S->W4[t][(j + 32) * 2];
            const float bo0 = S->B4[t * 2], bo1 = S->B4[t * 2 + 1];
#pragma unroll
            for (int g = 0; g < 12; g++) {
                float p0 = xj[g] * m0.x + xj32[g] * m1.x;
                float p1 = xj[g] * m0.y + xj32[g] * m1.y;
                u64 pk = packf2(p0, p1);
#pragma unroll
                for (int off = 16; off; off >>= 1)
                    pk = fadd2(pk, __shfl_xor_sync(0xffffffffu, pk, off));
                float2 o = unpk(pk);
                const bool valid = (gb + g) < G;
                if (t == 0) {
                    if (j < 5 && valid) {
                        float o0 = tanhf(o.x + bo0), o1 = tanhf(o.y + bo1);
                        *(float2*)&out[(size_t)(gb + g) * 12 + j * 2] = make_float2(o0, o1);
                    }
                } else {
                    if (j == 0 && valid) {
                        float o0 = tanhf(o.x + bo0), o1 = tanhf(o.y + bo1);
                        *(float2*)&out[(size_t)(gb + g) * 12 + 10] = make_float2(o0, o1);
                    }
                }
            }
            __syncwarp();   // rsp reads done before next type restages
        }
    }
}

// ---------------------------------------------------------------------------
extern "C" void kernel_launch(void* const* d_in, const int* in_sizes, int n_in,
                              void* d_out, int out_size) {
    const float* obs = (const float*)d_in[0];
    const float* Wp1 = (const float*)d_in[1];
    const float* bp1 = (const float*)d_in[2];
    const float* Ws1 = (const float*)d_in[3];
    const float* Wn1 = (const float*)d_in[4];
    const float* b1  = (const float*)d_in[5];
    const float* Wp2 = (const float*)d_in[6];
    const float* bp2 = (const float*)d_in[7];
    const float* Ws2 = (const float*)d_in[8];
    const float* Wn2 = (const float*)d_in[9];
    const float* b2  = (const float*)d_in[10];
    const float* MW1 = (const float*)d_in[11];
    const float* Mb1 = (const float*)d_in[12];
    const float* MW2 = (const float*)d_in[13];
    const float* Mb2 = (const float*)d_in[14];
    const float* MW3 = (const float*)d_in[15];
    const float* Mb3 = (const float*)d_in[16];
    const float* MW4 = (const float*)d_in[17];
    const float* Mb4 = (const float*)d_in[18];
    float* out = (float*)d_out;

    const int G = in_sizes[0] / 384;

    cudaFuncSetAttribute(conv_kernel, cudaFuncAttributeMaxDynamicSharedMemorySize,
                         (int)sizeof(SmemConv));
    cudaFuncSetAttribute(mlp_kernel, cudaFuncAttributeMaxDynamicSharedMemorySize,
                         (int)sizeof(SmemMlp));

    conv_kernel<<<148, 512, sizeof(SmemConv)>>>(obs, Wp1, bp1, Ws1, Wn1, b1,
                                                Wp2, bp2, Ws2, Wn2, b2, G);
    mlp_kernel<<<148, 512, sizeof(SmemMlp)>>>(MW1, Mb1, MW2, Mb2, MW3, Mb3,
                                              MW4, Mb4, out, G);
}